// round 9
// baseline (speedup 1.0000x reference)
#include <cuda_runtime.h>

#define NB 128      // batches
#define NP 27       // centers (3^3)
#define NN 8192     // points per batch
#define NS 512      // nsample
#define RAD2 0.0625f
#define BOXLIM 0.501f   // conservative candidate box: max|c_d| + r + margin

#define TPTS 256                 // points per compaction tile
#define NTILE (NN / TPTS)        // 32 tiles per batch

// ---- static scratch (no runtime allocation allowed) ----
__device__ float4 g_cand4[(size_t)NB * NN];        // compacted candidates (x,y,z,0), order-preserving
__device__ int    g_tilecnt[NB * NTILE];           // box-candidate count per tile
__device__ int    g_cnt[NB];                       // candidates per batch

// ============================================================
// Kernel 1: per-tile candidate count. grid = NB*NTILE, 256 thr.
// ============================================================
__global__ __launch_bounds__(TPTS) void count_kernel(const float* __restrict__ xyz)
{
    const int tile = blockIdx.x;
    const int b = tile >> 5;           // /NTILE
    const int t = tile & (NTILE - 1);
    const float* pts = xyz + (size_t)b * (NN * 3) + (size_t)t * (TPTS * 3);
    const int tid = threadIdx.x;

    const float x = pts[tid * 3 + 0];
    const float y = pts[tid * 3 + 1];
    const float z = pts[tid * 3 + 2];
    const bool m = (fabsf(x) <= BOXLIM) && (fabsf(y) <= BOXLIM) && (fabsf(z) <= BOXLIM);

    const int c = __syncthreads_count(m);
    if (tid == 0) g_tilecnt[tile] = c;
}

// ============================================================
// Kernel 2: per-tile order-preserving scatter into g_cand4.
// grid = NB*NTILE, 256 thr. Tile base offset = sum of preceding
// tile counts in this batch (L1-hot reads).
// ============================================================
#define SWARP (TPTS / 32)

__global__ __launch_bounds__(TPTS) void scatter_kernel(const float* __restrict__ xyz)
{
    const int tile = blockIdx.x;
    const int b = tile >> 5;
    const int t = tile & (NTILE - 1);
    const float* pts = xyz + (size_t)b * (NN * 3) + (size_t)t * (TPTS * 3);
    float4* dst = g_cand4 + (size_t)b * NN;

    __shared__ int s_wcnt[SWARP];

    const int tid  = threadIdx.x;
    const int lane = tid & 31;
    const int warp = tid >> 5;

    // exclusive prefix of preceding tile counts (uniform, redundant across threads)
    int base = 0;
    const int* tc = g_tilecnt + b * NTILE;
    for (int w = 0; w < t; w++) base += tc[w];

    const float x = pts[tid * 3 + 0];
    const float y = pts[tid * 3 + 1];
    const float z = pts[tid * 3 + 2];
    const bool m = (fabsf(x) <= BOXLIM) && (fabsf(y) <= BOXLIM) && (fabsf(z) <= BOXLIM);
    const unsigned bal = __ballot_sync(0xffffffffu, m);

    if (lane == 0) s_wcnt[warp] = __popc(bal);
    __syncthreads();

    int off = base;
    int tot = 0;
    #pragma unroll
    for (int w = 0; w < SWARP; w++) {
        const int c = s_wcnt[w];
        if (w < warp) off += c;
        tot += c;
    }

    if (m) {
        const int slot = off + __popc(bal & ((1u << lane) - 1u));
        dst[slot] = make_float4(x, y, z, 0.0f);
    }

    // last tile of each batch publishes the total candidate count
    if (t == NTILE - 1 && tid == 0) g_cnt[b] = base + tot;
}

// ============================================================
// Kernel 3: ball query + group over candidates only.
// 1 CTA per (batch, center). 512 threads -> usually 1 chunk.
// ============================================================
#define NT 512
#define NWARP (NT / 32)

__global__ __launch_bounds__(NT) void ballgroup_kernel(
    const float* __restrict__ xyz,
    const float* __restrict__ centers,
    float* __restrict__ out)
{
    const int bp = blockIdx.x;
    const int b  = bp / NP;
    const int p  = bp - b * NP;

    const float cx = centers[p * 3 + 0];
    const float cy = centers[p * 3 + 1];
    const float cz = centers[p * 3 + 2];
    // c2 in the reference's association order (no fma)
    const float c2 = __fadd_rn(__fadd_rn(__fmul_rn(cx, cx), __fmul_rn(cy, cy)),
                               __fmul_rn(cz, cz));

    const float*  pts0 = xyz + (size_t)b * (NN * 3);   // pad default (point 0)
    const float4* src  = g_cand4 + (size_t)b * NN;     // candidates, original order
    const int cnt = g_cnt[b];
    float* o = out + (size_t)bp * (NS * 3);

    __shared__ int   s_wcnt[NWARP];
    __shared__ float s_first[3];

    const int tid  = threadIdx.x;
    const int lane = tid & 31;
    const int warp = tid >> 5;

    if (tid == 0) {
        // default pad: first_idx = 0 when no match (argmax of all-false)
        s_first[0] = __fsub_rn(pts0[0], cx);
        s_first[1] = __fsub_rn(pts0[1], cy);
        s_first[2] = __fsub_rn(pts0[2], cz);
    }

    int base = 0;
    for (int chunk = 0; chunk < cnt; chunk += NT) {
        const int i = chunk + tid;
        const bool valid = (i < cnt);
        const float4 pt = src[valid ? i : 0];
        const float x = pt.x, y = pt.y, z = pt.z;

        // dist2 = (x2 + c2) - 2*xc, exactly as the reference (mul/add, no fma)
        const float x2 = __fadd_rn(__fadd_rn(__fmul_rn(x, x), __fmul_rn(y, y)),
                                   __fmul_rn(z, z));
        const float xc = __fadd_rn(__fadd_rn(__fmul_rn(cx, x), __fmul_rn(cy, y)),
                                   __fmul_rn(cz, z));
        const float d2 = __fsub_rn(__fadd_rn(x2, c2), __fmul_rn(2.0f, xc));

        const bool m = valid && (d2 < RAD2);
        const unsigned bal = __ballot_sync(0xffffffffu, m);

        __syncthreads();                 // protect s_wcnt from previous iteration
        if (lane == 0) s_wcnt[warp] = __popc(bal);
        __syncthreads();

        int off = base;
        int tot = 0;
        #pragma unroll
        for (int w = 0; w < NWARP; w++) {
            const int c = s_wcnt[w];
            if (w < warp) off += c;
            tot += c;
        }

        if (m) {
            const int slot = off + __popc(bal & ((1u << lane) - 1u));
            if (slot < NS) {
                const float ox = __fsub_rn(x, cx);
                const float oy = __fsub_rn(y, cy);
                const float oz = __fsub_rn(z, cz);
                o[slot * 3 + 0] = ox;
                o[slot * 3 + 1] = oy;
                o[slot * 3 + 2] = oz;
                if (slot == 0) {
                    s_first[0] = ox;
                    s_first[1] = oy;
                    s_first[2] = oz;
                }
            }
        }

        base += tot;
        if (base >= NS) break;
    }

    __syncthreads();
    const int count = base < NS ? base : NS;
    const float f0 = s_first[0];
    const float f1 = s_first[1];
    const float f2 = s_first[2];

    // ---- pad fill of float range [count*3, NS*3) with repeating (f0,f1,f2) ----
    const int start = count * 3;                 // <= 1536
    const int head  = (4 - (start & 3)) & 3;     // scalars to reach 16B alignment

    if (tid < head && start + tid < NS * 3) {
        const int fi = start + tid;
        const int d = fi % 3;
        o[fi] = (d == 0) ? f0 : (d == 1) ? f1 : f2;
    }

    // vectorized body: float index fi = 4*v, pattern index = v % 3
    float4 pat[3];
    pat[0] = make_float4(f0, f1, f2, f0);
    pat[1] = make_float4(f1, f2, f0, f1);
    pat[2] = make_float4(f2, f0, f1, f2);

    const int vstart = (start + head) >> 2;
    float4* o4 = reinterpret_cast<float4*>(o);
    for (int v = vstart + tid; v < (NS * 3) / 4; v += NT) {
        o4[v] = pat[v % 3];
    }
}

extern "C" void kernel_launch(void* const* d_in, const int* in_sizes, int n_in,
                              void* d_out, int out_size)
{
    const float* xyz     = (const float*)d_in[0];   // [128, 8192, 3]
    const float* centers = (const float*)d_in[1];   // [1, 27, 3]
    float* out = (float*)d_out;                      // [3456, 512, 3]

    count_kernel<<<NB * NTILE, TPTS>>>(xyz);
    scatter_kernel<<<NB * NTILE, TPTS>>>(xyz);
    ballgroup_kernel<<<NB * NP, NT>>>(xyz, centers, out);
}

// round 10
// speedup vs baseline: 1.3053x; 1.3053x over previous
#include <cuda_runtime.h>

#define NB 128      // batches
#define NP 27       // centers (3^3)
#define NN 8192     // points per batch
#define NS 512      // nsample
#define RAD2 0.0625f
#define BOXLIM 0.501f   // conservative candidate box: max|c_d| + r + margin

#define TPTS 1024                // points per compaction tile
#define NTILE (NN / TPTS)        // 8 tiles per batch

// ---- static scratch (no runtime allocation allowed) ----
__device__ float4 g_cand4[(size_t)NB * NN];   // per-tile locally-compacted candidates
__device__ int    g_tilecnt[NB * NTILE];      // candidate count per tile

// ============================================================
// Kernel 1: fused single-pass, per-tile order-preserving local
// compaction. grid = NB*NTILE = 1024, 256 thr, 4 points/thread.
// ============================================================
#define ST 256
#define SWARP (ST / 32)

__device__ __forceinline__ bool in_box(float x, float y, float z) {
    return (fabsf(x) <= BOXLIM) && (fabsf(y) <= BOXLIM) && (fabsf(z) <= BOXLIM);
}

__global__ __launch_bounds__(ST) void scatter_kernel(const float* __restrict__ xyz)
{
    const int tile = blockIdx.x;
    const int b = tile >> 3;              // / NTILE
    const int t = tile & (NTILE - 1);
    // tile base: b*NN*3 + t*TPTS*3 floats = multiple of 12288B -> 16B aligned
    const float4* src4 = reinterpret_cast<const float4*>(
        xyz + (size_t)b * (NN * 3) + (size_t)t * (TPTS * 3));
    float4* dst = g_cand4 + (size_t)b * NN + (size_t)t * TPTS;

    __shared__ int s_w[SWARP];

    const int tid  = threadIdx.x;
    const int lane = tid & 31;
    const int warp = tid >> 5;

    // 4 consecutive points per thread: floats [12*tid, 12*tid+12)
    const float4 va = src4[tid * 3 + 0];
    const float4 vb = src4[tid * 3 + 1];
    const float4 vc = src4[tid * 3 + 2];
    // p0=(va.x,va.y,va.z) p1=(va.w,vb.x,vb.y) p2=(vb.z,vb.w,vc.x) p3=(vc.y,vc.z,vc.w)
    const bool m0 = in_box(va.x, va.y, va.z);
    const bool m1 = in_box(va.w, vb.x, vb.y);
    const bool m2 = in_box(vb.z, vb.w, vc.x);
    const bool m3 = in_box(vc.y, vc.z, vc.w);

    const int c = (int)m0 + (int)m1 + (int)m2 + (int)m3;

    // warp inclusive scan of per-thread counts (order = lane order = point order)
    int inc = c;
    #pragma unroll
    for (int d = 1; d < 32; d <<= 1) {
        const int v = __shfl_up_sync(0xffffffffu, inc, d);
        if (lane >= d) inc += v;
    }
    if (lane == 31) s_w[warp] = inc;     // warp total
    __syncthreads();

    int base = 0, tot = 0;
    #pragma unroll
    for (int w = 0; w < SWARP; w++) {
        const int v = s_w[w];
        if (w < warp) base += v;
        tot += v;
    }

    int s = base + (inc - c);            // exclusive position of this thread's first match
    if (m0) dst[s++] = make_float4(va.x, va.y, va.z, 0.0f);
    if (m1) dst[s++] = make_float4(va.w, vb.x, vb.y, 0.0f);
    if (m2) dst[s++] = make_float4(vb.z, vb.w, vc.x, 0.0f);
    if (m3) dst[s++] = make_float4(vc.y, vc.z, vc.w, 0.0f);

    if (tid == 0) g_tilecnt[tile] = tot;
}

// ============================================================
// Kernel 2: ball query + group over candidates.
// 1 CTA per (batch, center). 512 threads -> usually 1 chunk.
// Cross-tile order via smem prefix of the 8 tile counts.
// ============================================================
#define NT 512
#define NWARP (NT / 32)

__global__ __launch_bounds__(NT) void ballgroup_kernel(
    const float* __restrict__ xyz,
    const float* __restrict__ centers,
    float* __restrict__ out)
{
    const int bp = blockIdx.x;
    const int b  = bp / NP;
    const int p  = bp - b * NP;

    const float cx = centers[p * 3 + 0];
    const float cy = centers[p * 3 + 1];
    const float cz = centers[p * 3 + 2];
    // c2 in the reference's association order (no fma)
    const float c2 = __fadd_rn(__fadd_rn(__fmul_rn(cx, cx), __fmul_rn(cy, cy)),
                               __fmul_rn(cz, cz));

    const float*  pts0 = xyz + (size_t)b * (NN * 3);   // pad default (point 0)
    const float4* src  = g_cand4 + (size_t)b * NN;
    float* o = out + (size_t)bp * (NS * 3);

    __shared__ int   s_pref[NTILE + 1];
    __shared__ int   s_wcnt[NWARP];
    __shared__ float s_first[3];

    const int tid  = threadIdx.x;
    const int lane = tid & 31;
    const int warp = tid >> 5;

    if (tid == 0) {
        int acc = 0;
        #pragma unroll
        for (int w = 0; w < NTILE; w++) {
            s_pref[w] = acc;
            acc += g_tilecnt[b * NTILE + w];
        }
        s_pref[NTILE] = acc;
        // default pad: first_idx = 0 when no match (argmax of all-false)
        s_first[0] = __fsub_rn(pts0[0], cx);
        s_first[1] = __fsub_rn(pts0[1], cy);
        s_first[2] = __fsub_rn(pts0[2], cz);
    }
    __syncthreads();

    const int cnt = s_pref[NTILE];

    int base = 0;
    for (int chunk = 0; chunk < cnt; chunk += NT) {
        const int i = chunk + tid;
        const bool valid = (i < cnt);
        const int ii = valid ? i : 0;

        // locate tile holding global candidate index ii
        int tile = 0;
        #pragma unroll
        for (int w = 1; w < NTILE; w++)
            if (ii >= s_pref[w]) tile = w;

        const float4 pt = src[tile * TPTS + (ii - s_pref[tile])];
        const float x = pt.x, y = pt.y, z = pt.z;

        // dist2 = (x2 + c2) - 2*xc, exactly as the reference (mul/add, no fma)
        const float x2 = __fadd_rn(__fadd_rn(__fmul_rn(x, x), __fmul_rn(y, y)),
                                   __fmul_rn(z, z));
        const float xc = __fadd_rn(__fadd_rn(__fmul_rn(cx, x), __fmul_rn(cy, y)),
                                   __fmul_rn(cz, z));
        const float d2 = __fsub_rn(__fadd_rn(x2, c2), __fmul_rn(2.0f, xc));

        const bool m = valid && (d2 < RAD2);
        const unsigned bal = __ballot_sync(0xffffffffu, m);

        __syncthreads();                 // protect s_wcnt from previous iteration
        if (lane == 0) s_wcnt[warp] = __popc(bal);
        __syncthreads();

        int off = base;
        int tot = 0;
        #pragma unroll
        for (int w = 0; w < NWARP; w++) {
            const int cwc = s_wcnt[w];
            if (w < warp) off += cwc;
            tot += cwc;
        }

        if (m) {
            const int slot = off + __popc(bal & ((1u << lane) - 1u));
            if (slot < NS) {
                const float ox = __fsub_rn(x, cx);
                const float oy = __fsub_rn(y, cy);
                const float oz = __fsub_rn(z, cz);
                o[slot * 3 + 0] = ox;
                o[slot * 3 + 1] = oy;
                o[slot * 3 + 2] = oz;
                if (slot == 0) {
                    s_first[0] = ox;
                    s_first[1] = oy;
                    s_first[2] = oz;
                }
            }
        }

        base += tot;
        if (base >= NS) break;
    }

    __syncthreads();
    const int count = base < NS ? base : NS;
    const float f0 = s_first[0];
    const float f1 = s_first[1];
    const float f2 = s_first[2];

    // ---- pad fill of float range [count*3, NS*3) with repeating (f0,f1,f2) ----
    const int start = count * 3;                 // <= 1536
    const int head  = (4 - (start & 3)) & 3;     // scalars to reach 16B alignment

    if (tid < head && start + tid < NS * 3) {
        const int fi = start + tid;
        const int d = fi % 3;
        o[fi] = (d == 0) ? f0 : (d == 1) ? f1 : f2;
    }

    // vectorized body: float index fi = 4*v, pattern index = v % 3
    float4 pat[3];
    pat[0] = make_float4(f0, f1, f2, f0);
    pat[1] = make_float4(f1, f2, f0, f1);
    pat[2] = make_float4(f2, f0, f1, f2);

    const int vstart = (start + head) >> 2;
    float4* o4 = reinterpret_cast<float4*>(o);
    for (int v = vstart + tid; v < (NS * 3) / 4; v += NT) {
        o4[v] = pat[v % 3];
    }
}

extern "C" void kernel_launch(void* const* d_in, const int* in_sizes, int n_in,
                              void* d_out, int out_size)
{
    const float* xyz     = (const float*)d_in[0];   // [128, 8192, 3]
    const float* centers = (const float*)d_in[1];   // [1, 27, 3]
    float* out = (float*)d_out;                      // [3456, 512, 3]

    scatter_kernel<<<NB * NTILE, ST>>>(xyz);
    ballgroup_kernel<<<NB * NP, NT>>>(xyz, centers, out);
}